// round 15
// baseline (speedup 1.0000x reference)
#include <cuda_runtime.h>
#include <cuda_fp16.h>
#include <cstdint>

#define B_  4
#define S_  2048
#define D_  1024
#define H_  16
#define DH_ 64
#define M_  (B_ * S_)   // 8192

// ---------------- device scratch: pre-swizzled tile images (hi-only) --------
__device__ unsigned char g_aimg[64 * 16 * 16384];
__device__ unsigned char g_bimg[3 * 8 * 16 * 16384];
__device__ unsigned char g_qimg[64 * 16 * 16384];
__device__ unsigned char g_kvimg[64 * 32 * 16384];   // Kh 8K | VTh 8K per s-tile

#define KVSTRIDE 16384
#define SWZ(c, r) ((((c) ^ ((r) & 7)) << 4))

// ---------------- helpers ----------------------------------------------------
static __device__ __forceinline__ uint32_t s2u(const void* p) {
    uint32_t a;
    asm("{ .reg .u64 t; cvta.to.shared.u64 t, %1; cvt.u32.u64 %0, t; }"
        : "=r"(a) : "l"(p));
    return a;
}

static __device__ __forceinline__ void mbar_init(uint32_t a, uint32_t cnt) {
    asm volatile("mbarrier.init.shared.b64 [%0], %1;" :: "r"(a), "r"(cnt) : "memory");
}
static __device__ __forceinline__ void mbar_expect_tx(uint32_t a, uint32_t bytes) {
    asm volatile("mbarrier.arrive.expect_tx.shared.b64 _, [%0], %1;"
                 :: "r"(a), "r"(bytes) : "memory");
}
static __device__ __forceinline__ void mbar_wait(uint32_t a, uint32_t parity) {
    asm volatile(
        "{\n\t.reg .pred P;\n\t"
        "W_%=:\n\t"
        "mbarrier.try_wait.parity.shared::cta.b64 P, [%0], %1;\n\t"
        "@!P bra W_%=;\n\t}"
        :: "r"(a), "r"(parity) : "memory");
}
static __device__ __forceinline__ void bulk_g2s(uint32_t dst, const void* src,
                                                uint32_t bytes, uint32_t mbar) {
    asm volatile(
        "cp.async.bulk.shared::cluster.global.mbarrier::complete_tx::bytes "
        "[%0], [%1], %2, [%3];"
        :: "r"(dst), "l"(__cvta_generic_to_global(src)), "r"(bytes), "r"(mbar)
        : "memory");
}
static __device__ __forceinline__ void nbar_arrive(int id, int cnt) {
    asm volatile("bar.arrive %0, %1;" :: "r"(id), "r"(cnt) : "memory");
}
static __device__ __forceinline__ void nbar_sync(int id, int cnt) {
    asm volatile("bar.sync %0, %1;" :: "r"(id), "r"(cnt) : "memory");
}

#define LDSM4(r0, r1, r2, r3, a)                                            \
    asm volatile("ldmatrix.sync.aligned.m8n8.x4.shared.b16 "                \
                 "{%0,%1,%2,%3}, [%4];"                                     \
                 : "=r"(r0), "=r"(r1), "=r"(r2), "=r"(r3) : "r"(a))

#define MMA16816(d, a, b0v, b1v)                                            \
    asm volatile("mma.sync.aligned.m16n8k16.row.col.f32.f16.f16.f32 "       \
                 "{%0,%1,%2,%3}, {%4,%5,%6,%7}, {%8,%9}, {%0,%1,%2,%3};"    \
                 : "+f"((d)[0]), "+f"((d)[1]), "+f"((d)[2]), "+f"((d)[3])   \
                 : "r"((a)[0]), "r"((a)[1]), "r"((a)[2]), "r"((a)[3]),      \
                   "r"(b0v), "r"(b1v))

static __device__ __forceinline__ uint32_t pkf(float a, float b) {
    __half2 h = __floats2half2_rn(a, b);
    return *(uint32_t*)&h;
}
static __device__ __forceinline__ float ex2(float x) {
    float r;
    asm("ex2.approx.f32 %0, %1;" : "=f"(r) : "f"(x));
    return r;
}

// ---------------------------------------------------------------------------
// Preprocessing: round X to fp16, write A tile image (hi only).
// ---------------------------------------------------------------------------
__global__ void xsplit(const float* __restrict__ x)
{
    int i = blockIdx.x * 256 + threadIdx.x;      // 8-float chunk index
    int l = i * 8;
    int m = l >> 10, k = l & (D_ - 1);
    float4 v0 = ((const float4*)x)[2 * i];
    float4 v1 = ((const float4*)x)[2 * i + 1];
    uint4 h4 = make_uint4(pkf(v0.x, v0.y), pkf(v0.z, v0.w),
                          pkf(v1.x, v1.y), pkf(v1.z, v1.w));
    size_t base = ((size_t)(m >> 7) * 16 + (k >> 6)) * 16384;
    int r = m & 127, c = (k >> 3) & 7;
    *(uint4*)&g_aimg[base + r * 128 + SWZ(c, r)] = h4;
}

// ---------------------------------------------------------------------------
// Preprocessing: transpose W, fp16 round, write B tile image.
// ---------------------------------------------------------------------------
__global__ void wsplit(const float* __restrict__ Wq,
                       const float* __restrict__ Wk,
                       const float* __restrict__ Wv)
{
    __shared__ float t[32][33];
    const int z = blockIdx.z;
    const float* W = (z == 0) ? Wq : (z == 1) ? Wk : Wv;
    const int n  = blockIdx.x * 32 + threadIdx.x;
    const int k0 = blockIdx.y * 32;
    #pragma unroll
    for (int dy = 0; dy < 32; dy += 8) {
        int k = k0 + threadIdx.y + dy;
        t[threadIdx.y + dy][threadIdx.x] = W[(size_t)k * D_ + n];
    }
    __syncthreads();
    const int kk = k0 + threadIdx.x;
    #pragma unroll
    for (int dy = 0; dy < 32; dy += 8) {
        int nn = blockIdx.x * 32 + threadIdx.y + dy;
        float v = t[threadIdx.x][threadIdx.y + dy];
        size_t base = ((size_t)(z * 8 + (nn >> 7)) * 16 + (kk >> 6)) * 16384;
        int r = nn & 127, c = (kk >> 3) & 7, byb = (kk & 7) * 2;
        *(unsigned short*)&g_bimg[base + r * 128 + SWZ(c, r) + byb] =
            __half_as_ushort(__float2half_rn(v));
    }
}

// ---------------------------------------------------------------------------
// QKV GEMM: 1-term fp16 (Ah*Bh).  BK=64 chunks, 16 iters, 3x32KB stages.
// z=2 epilogue writes V^T fp16 directly into the KV image.  (round-10 verified)
// ---------------------------------------------------------------------------
#define NK     16
#define SMEM_G (1024 + 3 * 32768)

__global__ __launch_bounds__(256, 2) void qkv_gemm_mma()
{
    extern __shared__ char smem[];
    const uint32_t sb = s2u(smem);
    const int tid  = threadIdx.x;
    const int warp = tid >> 5;
    const int lane = tid & 31;
    const int wm   = warp & 1;
    const int wn   = warp >> 1;

    const int n0 = blockIdx.x * 128;
    const int m0 = blockIdx.y * 128;
    const int z  = blockIdx.z;

    if (tid == 0) {
        mbar_init(sb + 0, 1);
        mbar_init(sb + 8, 1);
        mbar_init(sb + 16, 1);
    }
    __syncthreads();

    const unsigned char* Asrc = g_aimg + (size_t)blockIdx.y * 16 * 16384;
    const unsigned char* Bsrc = g_bimg + (size_t)(z * 8 + blockIdx.x) * 16 * 16384;

    if (tid == 0) {
        #pragma unroll
        for (int s = 0; s < 3; s++) {
            mbar_expect_tx(sb + 8 * s, 32768);
            bulk_g2s(sb + 1024 + s * 32768,         Asrc + s * 16384, 16384, sb + 8 * s);
            bulk_g2s(sb + 1024 + s * 32768 + 16384, Bsrc + s * 16384, 16384, sb + 8 * s);
        }
    }

    float acc[4][4][4];
    #pragma unroll
    for (int mi = 0; mi < 4; mi++)
        #pragma unroll
        for (int ni = 0; ni < 4; ni++)
            #pragma unroll
            for (int r = 0; r < 4; r++) acc[mi][ni][r] = 0.f;

    int aRow[4];
    #pragma unroll
    for (int mi = 0; mi < 4; mi++) aRow[mi] = wm * 64 + mi * 16 + (lane & 15);
    const int aG = (lane >> 4);
    int bRow[2];
    #pragma unroll
    for (int p = 0; p < 2; p++) bRow[p] = wn * 32 + p * 16 + (lane & 7) + ((lane & 16) >> 1);
    const int bG = (lane >> 3) & 1;

    for (int i = 0; i < NK; i++) {
        const int s = i % 3;
        mbar_wait(sb + 8 * s, (uint32_t)((i / 3) & 1));

        const uint32_t aBase = sb + 1024 + s * 32768;
        const uint32_t bBase = aBase + 16384;

        #pragma unroll
        for (int kstep = 0; kstep < 4; kstep++) {
            const int g0 = kstep * 2;

            uint32_t ah[4][4], bh2[2][4];
            #pragma unroll
            for (int mi = 0; mi < 4; mi++) {
                int r = aRow[mi];
                uint32_t ad = aBase + r * 128 + (((g0 + aG) ^ (r & 7)) << 4);
                LDSM4(ah[mi][0], ah[mi][1], ah[mi][2], ah[mi][3], ad);
            }
            #pragma unroll
            for (int p = 0; p < 2; p++) {
                int r = bRow[p];
                uint32_t bd = bBase + r * 128 + (((g0 + bG) ^ (r & 7)) << 4);
                LDSM4(bh2[p][0], bh2[p][1], bh2[p][2], bh2[p][3], bd);
            }
            #pragma unroll
            for (int mi = 0; mi < 4; mi++)
                #pragma unroll
                for (int ni = 0; ni < 4; ni++)
                    MMA16816(acc[mi][ni], ah[mi], bh2[ni >> 1][(ni & 1) * 2], bh2[ni >> 1][(ni & 1) * 2 + 1]);
        }

        __syncthreads();
        const int nx = i + 3;
        if (nx < NK && tid == 0) {
            mbar_expect_tx(sb + 8 * s, 32768);
            bulk_g2s(aBase, Asrc + nx * 16384, 16384, sb + 8 * s);
            bulk_g2s(bBase, Bsrc + nx * 16384, 16384, sb + 8 * s);
        }
    }

    // epilogue: z=0 -> Q image; z=1 -> Kh in KV image; z=2 -> V^T in KV image
    #pragma unroll
    for (int mi = 0; mi < 4; mi++) {
        #pragma unroll
        for (int ni = 0; ni < 4; ni++) {
            int m = m0 + wm * 64 + mi * 16 + (lane >> 2);
            int n = n0 + wn * 32 + ni * 8 + ((lane & 3) << 1);
            int h  = n >> 6;
            int dh = n & (DH_ - 1);
            #pragma unroll
            for (int half = 0; half < 2; half++) {
                int mm = m + half * 8;
                int b  = mm >> 11;
                int sq = mm & (S_ - 1);
                float v0 = acc[mi][ni][half * 2];
                float v1 = acc[mi][ni][half * 2 + 1];
                size_t bh = (size_t)b * H_ + h;
                if (z == 0) {
                    size_t ob = (bh * 16 + (sq >> 7)) * 16384
                              + (size_t)(sq & 127) * 128
                              + SWZ(dh >> 3, sq & 127) + (dh & 7) * 2;
                    *(uint32_t*)&g_qimg[ob] = pkf(v0, v1);
                } else if (z == 1) {
                    size_t ob = (bh * 32 + (sq >> 6)) * (size_t)KVSTRIDE
                              + (size_t)(sq & 63) * 128
                              + SWZ(dh >> 3, sq & 63) + (dh & 7) * 2;
                    *(uint32_t*)&g_kvimg[ob] = pkf(v0, v1);
                } else {
                    int sl = sq & 63;
                    size_t vb = (bh * 32 + (sq >> 6)) * (size_t)KVSTRIDE + 8192;
                    uint32_t o0 = (uint32_t)(dh * 128 + SWZ((sl >> 3) & 7, dh) + (sl & 7) * 2);
                    uint32_t o1 = (uint32_t)((dh + 1) * 128 + SWZ((sl >> 3) & 7, dh + 1) + (sl & 7) * 2);
                    *(unsigned short*)&g_kvimg[vb + o0] = __half_as_ushort(__float2half_rn(v0));
                    *(unsigned short*)&g_kvimg[vb + o1] = __half_as_ushort(__float2half_rn(v1));
                }
            }
        }
    }
}

// ---------------------------------------------------------------------------
// Tensor-core flash attention: 256 threads, 8 warps x 16 q-rows.
// 4 KV stages.  Producer/consumer via NAMED barriers:
//   warps 1-7: bar.arrive((t&7), 256) after each tile (non-blocking);
//   warp 0:    bar.sync((t-2)&7, 256) before prefetching tile t+2
//              (waits for all other warps to finish tile t-2, the last
//               reader of the stage being recycled; its own completion of
//               t-2 is implied by program order).
// Consumers never hit a blocking block barrier -> warps skew up to the
// 4-stage ring depth, overlapping MUFU/pack phases with MMA phases.
// smem: mbars @ [0,1024); KV stages @1024+st*16K (4); Q @1024+64K.
// ---------------------------------------------------------------------------
#define NKT    32
#define OFF_Q  (1024 + 4 * KVSTRIDE)
#define SMEM_A (OFF_Q + 16384)
#define L2E    1.4426950408889634f
#define CSC    (0.0625f * L2E)

__global__ __launch_bounds__(256, 2) void attn_mma(float* __restrict__ out)
{
    extern __shared__ char sm[];
    const uint32_t sb = s2u(sm);
    const int tid = threadIdx.x, warp = tid >> 5, lane = tid & 31;
    const int b = blockIdx.z, h = blockIdx.y, q0 = blockIdx.x * 128;
    const size_t bh = (size_t)(b * H_ + h);

    const unsigned char* Qsrc  = g_qimg + (bh * 16 + blockIdx.x) * 16384;
    const unsigned char* KVsrc = g_kvimg + bh * 32 * (size_t)KVSTRIDE;

    if (tid == 0) {
        mbar_init(sb + 0, 1);      // Q
        #pragma unroll
        for (int s = 0; s < 4; s++)
            mbar_init(sb + 8 + 8 * s, 1);   // KV stage s
    }
    __syncthreads();

    if (tid == 0) {
        mbar_expect_tx(sb, 16384);
        bulk_g2s(sb + OFF_Q, Qsrc, 16384, sb);
        #pragma unroll
        for (int s = 0; s < 2; s++) {
            mbar_expect_tx(sb + 8 + 8 * s, KVSTRIDE);
            bulk_g2s(sb + 1024 + s * KVSTRIDE, KVsrc + (size_t)s * KVSTRIDE,
                     KVSTRIDE, sb + 8 + 8 * s);
        }
    }

    mbar_wait(sb, 0);

    uint32_t Qh[4][4];
    {
        const int ar = warp * 16 + (lane & 15);
        const int ag = lane >> 4;
        #pragma unroll
        for (int kc = 0; kc < 4; kc++) {
            uint32_t ad = sb + OFF_Q + ar * 128 + (((kc * 2 + ag) ^ (ar & 7)) << 4);
            LDSM4(Qh[kc][0], Qh[kc][1], Qh[kc][2], Qh[kc][3], ad);
        }
    }

    float o[8][4];
    #pragma unroll
    for (int j = 0; j < 8; j++)
        #pragma unroll
        for (int r = 0; r < 4; r++) o[j][r] = 0.f;
    float mm0 = 0.f, mm1 = 0.f;      // -max * log2(e), frozen after tile 0
    float l0 = 0.f, l1 = 0.f;

    const int brb = (lane & 7) + ((lane & 16) >> 1);
    const int bg  = (lane >> 3) & 1;

    for (int t = 0; t < NKT; t++) {
        // Warp 0: recycle-gate + prefetch of tile t+2 into stage (t+2)&3.
        if (warp == 0 && t + 2 < NKT) {
            if (t >= 2) nbar_sync((t - 2) & 7, 256);
            if (lane == 0) {
                const int st = (t + 2) & 3;
                mbar_expect_tx(sb + 8 + 8 * st, KVSTRIDE);
                bulk_g2s(sb + 1024 + st * KVSTRIDE,
                         KVsrc + (size_t)(t + 2) * KVSTRIDE,
                         KVSTRIDE, sb + 8 + 8 * st);
            }
        }
        mbar_wait(sb + 8 + 8 * (t & 3), (uint32_t)((t >> 2) & 1));

        const uint32_t kvb = sb + 1024 + (t & 3) * KVSTRIDE;

        // ---- S = Qh Kh^T (1 term) ----
        float s[8][4];
        #pragma unroll
        for (int j = 0; j < 8; j++)
            #pragma unroll
            for (int r = 0; r < 4; r++) s[j][r] = 0.f;

        #pragma unroll
        for (int kc = 0; kc < 4; kc++) {
            const int g = kc * 2 + bg;
            uint32_t kf[4][4];
            #pragma unroll
            for (int nt = 0; nt < 4; nt++) {
                int r = nt * 16 + brb;
                uint32_t off = r * 128 + ((g ^ (r & 7)) << 4);
                LDSM4(kf[nt][0], kf[nt][1], kf[nt][2], kf[nt][3], kvb + off);
            }
            #pragma unroll
            for (int nt = 0; nt < 4; nt++)
                #pragma unroll
                for (int h2 = 0; h2 < 2; h2++) {
                    int ni = nt * 2 + h2;
                    MMA16816(s[ni], Qh[kc], kf[nt][h2 * 2], kf[nt][h2 * 2 + 1]);
                }
        }

        // ---- frozen max (tile 0 only); store as -m*log2e ----
        if (t == 0) {
            float mt0 = -1e30f, mt1 = -1e30f;
            #pragma unroll
            for (int j = 0; j < 8; j++) {
                mt0 = fmaxf(mt0, fmaxf(s[j][0], s[j][1]));
                mt1 = fmaxf(mt1, fmaxf(s[j][2], s[j][3]));
            }
            mt0 *= 0.0625f; mt1 *= 0.0625f;
            mt0 = fmaxf(mt0, __shfl_xor_sync(0xFFFFFFFFu, mt0, 1));
            mt0 = fmaxf(mt0, __shfl_xor_sync(0xFFFFFFFFu, mt0, 2));
            mt1 = fmaxf(mt1, __shfl_xor_sync(0xFFFFFFFFu, mt1, 1));
            mt1 = fmaxf(mt1, __shfl_xor_sync(0xFFFFFFFFu, mt1, 2));
            mm0 = -mt0 * L2E;
            mm1 = -mt1 * L2E;
        }

        // ---- fused: per key-group exp + pack + PV MMAs ----
        #pragma unroll
        for (int kc = 0; kc < 4; kc++) {
            const int g = kc * 2 + bg;
            uint32_t vh4[4][4];
            #pragma unroll
            for (int nt = 0; nt < 4; nt++) {
                int r = nt * 16 + brb;
                uint32_t off = r * 128 + ((g ^ (r & 7)) << 4);
                LDSM4(vh4[nt][0], vh4[nt][1], vh4[nt][2], vh4[nt][3], kvb + 8192 + off);
            }

            float p00 = ex2(fmaf(s[2 * kc][0],     CSC, mm0));
            float p01 = ex2(fmaf(s[2 * kc][1],     CSC, mm0));
            float p02 = ex2(fmaf(s[2 * kc][2],     CSC, mm1));
            float p03 = ex2(fmaf(s[2 * kc][3],     CSC, mm1));
            float p10 = ex2(fmaf(s[2 * kc + 1][0], CSC, mm0));
            float p11 = ex2(fmaf(s[2 * kc + 1][1], CSC, mm0));
            float p12 = ex2(fmaf(s[2 * kc + 1][2], CSC, mm1));
            float p13 = ex2(fmaf(s[2 * kc + 1][3], CSC, mm1));
            l0 += p00 + p01 + p10 + p11;
            l1 += p02 + p03 + p12 + p13;

            uint32_t Ahf[4];
            Ahf[0] = pkf(p00, p01);
            Ahf[1] = pkf(p02, p03);
            Ahf[2] = pkf(p10, p11);
            Ahf[3] = pkf(p12, p13);

            #pragma unroll
            for (int nt = 0; nt < 4; nt++)
                #pragma unroll
                for (int h2 = 0; h2 < 2; h2++) {
                    int ni = nt * 2 + h2;
                    MMA16816(o[ni], Ahf, vh4[nt][h2 * 2], vh4[nt][h2 * 2 + 1]);
                }
        }

        // consumers signal tile completion (non-blocking)
        if (warp != 0) nbar_arrive(t & 7, 256);
    }

    // ---- epilogue ----
    l0 += __shfl_xor_sync(0xFFFFFFFFu, l0, 1);
    l0 += __shfl_xor_sync(0xFFFFFFFFu, l0, 2);
    l1 += __shfl_xor_sync(0xFFFFFFFFu, l1, 1);
    l1 += __shfl_xor_sync(0xFFFFFFFFu, l1, 2);
    const float i0 = 1.0f / l0, i1 = 1.0f / l1;

    const int q = q0 + warp * 16 + (lane >> 2);
    float* op = out + ((size_t)b * S_ + q) * D_ + h * DH_;
    #pragma unroll
    for (int j = 0; j < 8; j++) {
        int dh = j * 8 + ((lane & 3) << 1);
        *(float2*)(op + dh)          = make_float2(o[j][0] * i0, o[j][1] * i0);
        *(float2*)(op + 8 * D_ + dh) = make_float2(o[j][2] * i1, o[j][3] * i1);
    }
}

// ---------------------------------------------------------------------------
// Launch
// ---------------------------------------------------------------------------
extern "C" void kernel_launch(void* const* d_in, const int* in_sizes, int n_in,
                              void* d_out, int out_size)
{
    const float* x  = (const float*)d_in[0];
    const float* wq = (const float*)d_in[1];
    const float* wk = (const float*)d_in[2];
    const float* wv = (const float*)d_in[3];
    float* out = (float*)d_out;

    static bool attr_set = false;
    if (!attr_set) {
        cudaFuncSetAttribute(qkv_gemm_mma,
                             cudaFuncAttributeMaxDynamicSharedMemorySize, SMEM_G);
        cudaFuncSetAttribute(attn_mma,
                             cudaFuncAttributeMaxDynamicSharedMemorySize, SMEM_A);
        attr_set = true;
    }

    xsplit<<<(M_ * D_ / 8) / 256, 256>>>(x);
    wsplit<<<dim3(32, 32, 3), dim3(32, 8)>>>(wq, wk, wv);
    qkv_gemm_mma<<<dim3(D_ / 128, M_ / 128, 3), 256, SMEM_G>>>();
    attn_mma<<<dim3(S_ / 128, H_, B_), 256, SMEM_A>>>(out);
}

// round 16
// speedup vs baseline: 1.5545x; 1.5545x over previous
#include <cuda_runtime.h>
#include <cuda_fp16.h>
#include <cstdint>

#define B_  4
#define S_  2048
#define D_  1024
#define H_  16
#define DH_ 64
#define M_  (B_ * S_)   // 8192

// ---------------- device scratch: pre-swizzled tile images (hi-only) --------
__device__ unsigned char g_aimg[64 * 16 * 16384];
__device__ unsigned char g_bimg[3 * 8 * 16 * 16384];
__device__ unsigned char g_qimg[64 * 16 * 16384];
__device__ unsigned char g_kvimg[64 * 32 * 16384];   // Kh 8K | VTh 8K per s-tile

#define KVSTRIDE 16384
#define SWZ(c, r) ((((c) ^ ((r) & 7)) << 4))

// ---------------- helpers ----------------------------------------------------
static __device__ __forceinline__ uint32_t s2u(const void* p) {
    uint32_t a;
    asm("{ .reg .u64 t; cvta.to.shared.u64 t, %1; cvt.u32.u64 %0, t; }"
        : "=r"(a) : "l"(p));
    return a;
}

static __device__ __forceinline__ void mbar_init(uint32_t a, uint32_t cnt) {
    asm volatile("mbarrier.init.shared.b64 [%0], %1;" :: "r"(a), "r"(cnt) : "memory");
}
static __device__ __forceinline__ void mbar_expect_tx(uint32_t a, uint32_t bytes) {
    asm volatile("mbarrier.arrive.expect_tx.shared.b64 _, [%0], %1;"
                 :: "r"(a), "r"(bytes) : "memory");
}
static __device__ __forceinline__ void mbar_wait(uint32_t a, uint32_t parity) {
    asm volatile(
        "{\n\t.reg .pred P;\n\t"
        "W_%=:\n\t"
        "mbarrier.try_wait.parity.shared::cta.b64 P, [%0], %1;\n\t"
        "@!P bra W_%=;\n\t}"
        :: "r"(a), "r"(parity) : "memory");
}
static __device__ __forceinline__ void bulk_g2s(uint32_t dst, const void* src,
                                                uint32_t bytes, uint32_t mbar) {
    asm volatile(
        "cp.async.bulk.shared::cluster.global.mbarrier::complete_tx::bytes "
        "[%0], [%1], %2, [%3];"
        :: "r"(dst), "l"(__cvta_generic_to_global(src)), "r"(bytes), "r"(mbar)
        : "memory");
}

#define LDSM4(r0, r1, r2, r3, a)                                            \
    asm volatile("ldmatrix.sync.aligned.m8n8.x4.shared.b16 "                \
                 "{%0,%1,%2,%3}, [%4];"                                     \
                 : "=r"(r0), "=r"(r1), "=r"(r2), "=r"(r3) : "r"(a))

#define MMA16816(d, a, b0v, b1v)                                            \
    asm volatile("mma.sync.aligned.m16n8k16.row.col.f32.f16.f16.f32 "       \
                 "{%0,%1,%2,%3}, {%4,%5,%6,%7}, {%8,%9}, {%0,%1,%2,%3};"    \
                 : "+f"((d)[0]), "+f"((d)[1]), "+f"((d)[2]), "+f"((d)[3])   \
                 : "r"((a)[0]), "r"((a)[1]), "r"((a)[2]), "r"((a)[3]),      \
                   "r"(b0v), "r"(b1v))

static __device__ __forceinline__ uint32_t pkf(float a, float b) {
    __half2 h = __floats2half2_rn(a, b);
    return *(uint32_t*)&h;
}
// packed half2 exp2
static __device__ __forceinline__ uint32_t h2ex2(uint32_t x) {
    uint32_t r;
    asm("ex2.approx.f16x2 %0, %1;" : "=r"(r) : "r"(x));
    return r;
}

#define ONESH2 0x3C003C00u   // half2(1.0, 1.0)

// ---------------------------------------------------------------------------
// Preprocessing: round X to fp16, write A tile image (hi only).
// ---------------------------------------------------------------------------
__global__ void xsplit(const float* __restrict__ x)
{
    int i = blockIdx.x * 256 + threadIdx.x;      // 8-float chunk index
    int l = i * 8;
    int m = l >> 10, k = l & (D_ - 1);
    float4 v0 = ((const float4*)x)[2 * i];
    float4 v1 = ((const float4*)x)[2 * i + 1];
    uint4 h4 = make_uint4(pkf(v0.x, v0.y), pkf(v0.z, v0.w),
                          pkf(v1.x, v1.y), pkf(v1.z, v1.w));
    size_t base = ((size_t)(m >> 7) * 16 + (k >> 6)) * 16384;
    int r = m & 127, c = (k >> 3) & 7;
    *(uint4*)&g_aimg[base + r * 128 + SWZ(c, r)] = h4;
}

// ---------------------------------------------------------------------------
// Preprocessing: transpose W, fp16 round, write B tile image.
// ---------------------------------------------------------------------------
__global__ void wsplit(const float* __restrict__ Wq,
                       const float* __restrict__ Wk,
                       const float* __restrict__ Wv)
{
    __shared__ float t[32][33];
    const int z = blockIdx.z;
    const float* W = (z == 0) ? Wq : (z == 1) ? Wk : Wv;
    const int n  = blockIdx.x * 32 + threadIdx.x;
    const int k0 = blockIdx.y * 32;
    #pragma unroll
    for (int dy = 0; dy < 32; dy += 8) {
        int k = k0 + threadIdx.y + dy;
        t[threadIdx.y + dy][threadIdx.x] = W[(size_t)k * D_ + n];
    }
    __syncthreads();
    const int kk = k0 + threadIdx.x;
    #pragma unroll
    for (int dy = 0; dy < 32; dy += 8) {
        int nn = blockIdx.x * 32 + threadIdx.y + dy;
        float v = t[threadIdx.x][threadIdx.y + dy];
        size_t base = ((size_t)(z * 8 + (nn >> 7)) * 16 + (kk >> 6)) * 16384;
        int r = nn & 127, c = (kk >> 3) & 7, byb = (kk & 7) * 2;
        *(unsigned short*)&g_bimg[base + r * 128 + SWZ(c, r) + byb] =
            __half_as_ushort(__float2half_rn(v));
    }
}

// ---------------------------------------------------------------------------
// QKV GEMM: 1-term fp16 (Ah*Bh).  BK=64 chunks, 16 iters, 3x32KB stages.
// z=2 epilogue writes V^T fp16 directly into the KV image.  (round-10 verified)
// ---------------------------------------------------------------------------
#define NK     16
#define SMEM_G (1024 + 3 * 32768)

__global__ __launch_bounds__(256, 2) void qkv_gemm_mma()
{
    extern __shared__ char smem[];
    const uint32_t sb = s2u(smem);
    const int tid  = threadIdx.x;
    const int warp = tid >> 5;
    const int lane = tid & 31;
    const int wm   = warp & 1;
    const int wn   = warp >> 1;

    const int n0 = blockIdx.x * 128;
    const int m0 = blockIdx.y * 128;
    const int z  = blockIdx.z;

    if (tid == 0) {
        mbar_init(sb + 0, 1);
        mbar_init(sb + 8, 1);
        mbar_init(sb + 16, 1);
    }
    __syncthreads();

    const unsigned char* Asrc = g_aimg + (size_t)blockIdx.y * 16 * 16384;
    const unsigned char* Bsrc = g_bimg + (size_t)(z * 8 + blockIdx.x) * 16 * 16384;

    if (tid == 0) {
        #pragma unroll
        for (int s = 0; s < 3; s++) {
            mbar_expect_tx(sb + 8 * s, 32768);
            bulk_g2s(sb + 1024 + s * 32768,         Asrc + s * 16384, 16384, sb + 8 * s);
            bulk_g2s(sb + 1024 + s * 32768 + 16384, Bsrc + s * 16384, 16384, sb + 8 * s);
        }
    }

    float acc[4][4][4];
    #pragma unroll
    for (int mi = 0; mi < 4; mi++)
        #pragma unroll
        for (int ni = 0; ni < 4; ni++)
            #pragma unroll
            for (int r = 0; r < 4; r++) acc[mi][ni][r] = 0.f;

    int aRow[4];
    #pragma unroll
    for (int mi = 0; mi < 4; mi++) aRow[mi] = wm * 64 + mi * 16 + (lane & 15);
    const int aG = (lane >> 4);
    int bRow[2];
    #pragma unroll
    for (int p = 0; p < 2; p++) bRow[p] = wn * 32 + p * 16 + (lane & 7) + ((lane & 16) >> 1);
    const int bG = (lane >> 3) & 1;

    for (int i = 0; i < NK; i++) {
        const int s = i % 3;
        mbar_wait(sb + 8 * s, (uint32_t)((i / 3) & 1));

        const uint32_t aBase = sb + 1024 + s * 32768;
        const uint32_t bBase = aBase + 16384;

        #pragma unroll
        for (int kstep = 0; kstep < 4; kstep++) {
            const int g0 = kstep * 2;

            uint32_t ah[4][4], bh2[2][4];
            #pragma unroll
            for (int mi = 0; mi < 4; mi++) {
                int r = aRow[mi];
                uint32_t ad = aBase + r * 128 + (((g0 + aG) ^ (r & 7)) << 4);
                LDSM4(ah[mi][0], ah[mi][1], ah[mi][2], ah[mi][3], ad);
            }
            #pragma unroll
            for (int p = 0; p < 2; p++) {
                int r = bRow[p];
                uint32_t bd = bBase + r * 128 + (((g0 + bG) ^ (r & 7)) << 4);
                LDSM4(bh2[p][0], bh2[p][1], bh2[p][2], bh2[p][3], bd);
            }
            #pragma unroll
            for (int mi = 0; mi < 4; mi++)
                #pragma unroll
                for (int ni = 0; ni < 4; ni++)
                    MMA16816(acc[mi][ni], ah[mi], bh2[ni >> 1][(ni & 1) * 2], bh2[ni >> 1][(ni & 1) * 2 + 1]);
        }

        __syncthreads();
        const int nx = i + 3;
        if (nx < NK && tid == 0) {
            mbar_expect_tx(sb + 8 * s, 32768);
            bulk_g2s(aBase, Asrc + nx * 16384, 16384, sb + 8 * s);
            bulk_g2s(bBase, Bsrc + nx * 16384, 16384, sb + 8 * s);
        }
    }

    // epilogue: z=0 -> Q image; z=1 -> Kh in KV image; z=2 -> V^T in KV image
    #pragma unroll
    for (int mi = 0; mi < 4; mi++) {
        #pragma unroll
        for (int ni = 0; ni < 4; ni++) {
            int m = m0 + wm * 64 + mi * 16 + (lane >> 2);
            int n = n0 + wn * 32 + ni * 8 + ((lane & 3) << 1);
            int h  = n >> 6;
            int dh = n & (DH_ - 1);
            #pragma unroll
            for (int half = 0; half < 2; half++) {
                int mm = m + half * 8;
                int b  = mm >> 11;
                int sq = mm & (S_ - 1);
                float v0 = acc[mi][ni][half * 2];
                float v1 = acc[mi][ni][half * 2 + 1];
                size_t bh = (size_t)b * H_ + h;
                if (z == 0) {
                    size_t ob = (bh * 16 + (sq >> 7)) * 16384
                              + (size_t)(sq & 127) * 128
                              + SWZ(dh >> 3, sq & 127) + (dh & 7) * 2;
                    *(uint32_t*)&g_qimg[ob] = pkf(v0, v1);
                } else if (z == 1) {
                    size_t ob = (bh * 32 + (sq >> 6)) * (size_t)KVSTRIDE
                              + (size_t)(sq & 63) * 128
                              + SWZ(dh >> 3, sq & 63) + (dh & 7) * 2;
                    *(uint32_t*)&g_kvimg[ob] = pkf(v0, v1);
                } else {
                    int sl = sq & 63;
                    size_t vb = (bh * 32 + (sq >> 6)) * (size_t)KVSTRIDE + 8192;
                    uint32_t o0 = (uint32_t)(dh * 128 + SWZ((sl >> 3) & 7, dh) + (sl & 7) * 2);
                    uint32_t o1 = (uint32_t)((dh + 1) * 128 + SWZ((sl >> 3) & 7, dh + 1) + (sl & 7) * 2);
                    *(unsigned short*)&g_kvimg[vb + o0] = __half_as_ushort(__float2half_rn(v0));
                    *(unsigned short*)&g_kvimg[vb + o1] = __half_as_ushort(__float2half_rn(v1));
                }
            }
        }
    }
}

// ---------------------------------------------------------------------------
// Tensor-core flash attention: 256 threads, 8 warps x 16 q-rows.
// Round-14 sync (barrier every 2nd tile, 4 stages).  New this round:
//  - ex2.approx.f16x2 (exp two at a time; packed result IS the PV A frag)
//  - l computed by an extra MMA against B = ones (exact fp32 row sums of the
//    SAME f16 p used in PV -> numerator/denominator errors cancel); epilogue
//    shfl reductions removed.
// smem: mbars @ [0,1024); KV stages @1024+st*16K (4); Q @1024+64K.
// ---------------------------------------------------------------------------
#define NKT    32
#define OFF_Q  (1024 + 4 * KVSTRIDE)
#define SMEM_A (OFF_Q + 16384)
#define L2E    1.4426950408889634f
#define CSC    (0.0625f * L2E)

__global__ __launch_bounds__(256, 2) void attn_mma(float* __restrict__ out)
{
    extern __shared__ char sm[];
    const uint32_t sb = s2u(sm);
    const int tid = threadIdx.x, warp = tid >> 5, lane = tid & 31;
    const int b = blockIdx.z, h = blockIdx.y, q0 = blockIdx.x * 128;
    const size_t bh = (size_t)(b * H_ + h);

    const unsigned char* Qsrc  = g_qimg + (bh * 16 + blockIdx.x) * 16384;
    const unsigned char* KVsrc = g_kvimg + bh * 32 * (size_t)KVSTRIDE;

    if (tid == 0) {
        mbar_init(sb + 0, 1);      // Q
        #pragma unroll
        for (int s = 0; s < 4; s++)
            mbar_init(sb + 8 + 8 * s, 1);   // KV stage s
    }
    __syncthreads();

    if (tid == 0) {
        mbar_expect_tx(sb, 16384);
        bulk_g2s(sb + OFF_Q, Qsrc, 16384, sb);
        #pragma unroll
        for (int s = 0; s < 2; s++) {
            mbar_expect_tx(sb + 8 + 8 * s, KVSTRIDE);
            bulk_g2s(sb + 1024 + s * KVSTRIDE, KVsrc + (size_t)s * KVSTRIDE,
                     KVSTRIDE, sb + 8 + 8 * s);
        }
    }

    mbar_wait(sb, 0);

    uint32_t Qh[4][4];
    {
        const int ar = warp * 16 + (lane & 15);
        const int ag = lane >> 4;
        #pragma unroll
        for (int kc = 0; kc < 4; kc++) {
            uint32_t ad = sb + OFF_Q + ar * 128 + (((kc * 2 + ag) ^ (ar & 7)) << 4);
            LDSM4(Qh[kc][0], Qh[kc][1], Qh[kc][2], Qh[kc][3], ad);
        }
    }

    float o[8][4];
    #pragma unroll
    for (int j = 0; j < 8; j++)
        #pragma unroll
        for (int r = 0; r < 4; r++) o[j][r] = 0.f;
    float lacc[4] = {0.f, 0.f, 0.f, 0.f};   // row-sum accumulator (via ones-MMA)
    float mm0 = 0.f, mm1 = 0.f;              // -max * log2(e), frozen after tile 0

    const int brb = (lane & 7) + ((lane & 16) >> 1);
    const int bg  = (lane >> 3) & 1;

    for (int t = 0; t < NKT; t++) {
        // Block barrier + double-prefetch every second tile (round-14 protocol).
        if ((t & 1) == 0) {
            __syncthreads();
            if (tid == 0) {
                #pragma unroll
                for (int d = 2; d <= 3; d++) {
                    const int u = t + d;
                    if (u < NKT) {
                        const int st = u & 3;
                        mbar_expect_tx(sb + 8 + 8 * st, KVSTRIDE);
                        bulk_g2s(sb + 1024 + st * KVSTRIDE,
                                 KVsrc + (size_t)u * KVSTRIDE,
                                 KVSTRIDE, sb + 8 + 8 * st);
                    }
                }
            }
        }
        mbar_wait(sb + 8 + 8 * (t & 3), (uint32_t)((t >> 2) & 1));

        const uint32_t kvb = sb + 1024 + (t & 3) * KVSTRIDE;

        // ---- S = Qh Kh^T (1 term) ----
        float s[8][4];
        #pragma unroll
        for (int j = 0; j < 8; j++)
            #pragma unroll
            for (int r = 0; r < 4; r++) s[j][r] = 0.f;

        #pragma unroll
        for (int kc = 0; kc < 4; kc++) {
            const int g = kc * 2 + bg;
            uint32_t kf[4][4];
            #pragma unroll
            for (int nt = 0; nt < 4; nt++) {
                int r = nt * 16 + brb;
                uint32_t off = r * 128 + ((g ^ (r & 7)) << 4);
                LDSM4(kf[nt][0], kf[nt][1], kf[nt][2], kf[nt][3], kvb + off);
            }
            #pragma unroll
            for (int nt = 0; nt < 4; nt++)
                #pragma unroll
                for (int h2 = 0; h2 < 2; h2++) {
                    int ni = nt * 2 + h2;
                    MMA16816(s[ni], Qh[kc], kf[nt][h2 * 2], kf[nt][h2 * 2 + 1]);
                }
        }

        // ---- frozen max (tile 0 only); store as -m*log2e ----
        if (t == 0) {
            float mt0 = -1e30f, mt1 = -1e30f;
            #pragma unroll
            for (int j = 0; j < 8; j++) {
                mt0 = fmaxf(mt0, fmaxf(s[j][0], s[j][1]));
                mt1 = fmaxf(mt1, fmaxf(s[j][2], s[j][3]));
            }
            mt0 *= 0.0625f; mt1 *= 0.0625f;
            mt0 = fmaxf(mt0, __shfl_xor_sync(0xFFFFFFFFu, mt0, 1));
            mt0 = fmaxf(mt0, __shfl_xor_sync(0xFFFFFFFFu, mt0, 2));
            mt1 = fmaxf(mt1, __shfl_xor_sync(0xFFFFFFFFu, mt1, 1));
            mt1 = fmaxf(mt1, __shfl_xor_sync(0xFFFFFFFFu, mt1, 2));
            mm0 = -mt0 * L2E;
            mm1 = -mt1 * L2E;
        }

        // ---- fused: per key-group f16x2 exp + PV MMAs + ones-MMA for l ----
        #pragma unroll
        for (int kc = 0; kc < 4; kc++) {
            const int g = kc * 2 + bg;
            uint32_t vh4[4][4];
            #pragma unroll
            for (int nt = 0; nt < 4; nt++) {
                int r = nt * 16 + brb;
                uint32_t off = r * 128 + ((g ^ (r & 7)) << 4);
                LDSM4(vh4[nt][0], vh4[nt][1], vh4[nt][2], vh4[nt][3], kvb + 8192 + off);
            }

            // exponent args (fp32), packed pairwise, exp'd two-at-a-time
            uint32_t Ahf[4];
            Ahf[0] = h2ex2(pkf(fmaf(s[2 * kc][0],     CSC, mm0),
                               fmaf(s[2 * kc][1],     CSC, mm0)));
            Ahf[1] = h2ex2(pkf(fmaf(s[2 * kc][2],     CSC, mm1),
                               fmaf(s[2 * kc][3],     CSC, mm1)));
            Ahf[2] = h2ex2(pkf(fmaf(s[2 * kc + 1][0], CSC, mm0),
                               fmaf(s[2 * kc + 1][1], CSC, mm0)));
            Ahf[3] = h2ex2(pkf(fmaf(s[2 * kc + 1][2], CSC, mm1),
                               fmaf(s[2 * kc + 1][3], CSC, mm1)));

            // l: exact fp32 row-sums of the SAME f16 p (B = ones)
            MMA16816(lacc, Ahf, ONESH2, ONESH2);

            #pragma unroll
            for (int nt = 0; nt < 4; nt++)
                #pragma unroll
                for (int h2 = 0; h2 < 2; h2++) {
                    int ni = nt * 2 + h2;
                    MMA16816(o[ni], Ahf, vh4[nt][h2 * 2], vh4[nt][h2 * 2 + 1]);
                }
        }
    }

    // ---- epilogue (lacc[0] = full row sum, lacc[2] = row+8; no shfl needed) ----
    const float i0 = 1.0f / lacc[0], i1 = 1.0f / lacc[2];

    const int q = q0 + warp * 16 + (lane >> 2);
    float* op = out + ((size_t)b * S_ + q) * D_ + h * DH_;
    #pragma unroll
    for (int j = 0; j < 8; j++) {
        int dh = j * 8 + ((lane & 3) << 1);
        *(float2*)(op + dh)          = make_float2(o[j][0] * i0, o[j][1] * i0);
        *(float2*)(op + 8 * D_ + dh) = make_float2(o[j][2] * i1, o[j][3] * i1);
    }
}

// ---------------------------------------------------------------------------
// Launch
// ---------------------------------------------------------------------------
extern "C" void kernel_launch(void* const* d_in, const int* in_sizes, int n_in,
                              void* d_out, int out_size)
{
    const float* x  = (const float*)d_in[0];
    const float* wq = (const float*)d_in[1];
    const float* wk = (const float*)d_in[2];
    const float* wv = (const float*)d_in[3];
    float* out = (float*)d_out;

    static bool attr_set = false;
    if (!attr_set) {
        cudaFuncSetAttribute(qkv_gemm_mma,
                             cudaFuncAttributeMaxDynamicSharedMemorySize, SMEM_G);
        cudaFuncSetAttribute(attn_mma,
                             cudaFuncAttributeMaxDynamicSharedMemorySize, SMEM_A);
        attr_set = true;
    }

    xsplit<<<(M_ * D_ / 8) / 256, 256>>>(x);
    wsplit<<<dim3(32, 32, 3), dim3(32, 8)>>>(wq, wk, wv);
    qkv_gemm_mma<<<dim3(D_ / 128, M_ / 128, 3), 256, SMEM_G>>>();
    attn_mma<<<dim3(S_ / 128, H_, B_), 256, SMEM_A>>>(out);
}

// round 17
// speedup vs baseline: 1.5671x; 1.0081x over previous
#include <cuda_runtime.h>
#include <cuda_fp16.h>
#include <cstdint>

#define B_  4
#define S_  2048
#define D_  1024
#define H_  16
#define DH_ 64
#define M_  (B_ * S_)   // 8192

// ---------------- device scratch: pre-swizzled tile images (hi-only) --------
__device__ unsigned char g_aimg[64 * 16 * 16384];
__device__ unsigned char g_bimg[3 * 8 * 16 * 16384];
__device__ unsigned char g_qimg[64 * 16 * 16384];
__device__ unsigned char g_kvimg[64 * 32 * 16384];   // Kh 8K | VTh 8K per s-tile

#define KVSTRIDE 16384
#define SWZ(c, r) ((((c) ^ ((r) & 7)) << 4))

// ---------------- helpers ----------------------------------------------------
static __device__ __forceinline__ uint32_t s2u(const void* p) {
    uint32_t a;
    asm("{ .reg .u64 t; cvta.to.shared.u64 t, %1; cvt.u32.u64 %0, t; }"
        : "=r"(a) : "l"(p));
    return a;
}

static __device__ __forceinline__ void mbar_init(uint32_t a, uint32_t cnt) {
    asm volatile("mbarrier.init.shared.b64 [%0], %1;" :: "r"(a), "r"(cnt) : "memory");
}
static __device__ __forceinline__ void mbar_expect_tx(uint32_t a, uint32_t bytes) {
    asm volatile("mbarrier.arrive.expect_tx.shared.b64 _, [%0], %1;"
                 :: "r"(a), "r"(bytes) : "memory");
}
static __device__ __forceinline__ void mbar_wait(uint32_t a, uint32_t parity) {
    asm volatile(
        "{\n\t.reg .pred P;\n\t"
        "W_%=:\n\t"
        "mbarrier.try_wait.parity.shared::cta.b64 P, [%0], %1;\n\t"
        "@!P bra W_%=;\n\t}"
        :: "r"(a), "r"(parity) : "memory");
}
static __device__ __forceinline__ void bulk_g2s(uint32_t dst, const void* src,
                                                uint32_t bytes, uint32_t mbar) {
    asm volatile(
        "cp.async.bulk.shared::cluster.global.mbarrier::complete_tx::bytes "
        "[%0], [%1], %2, [%3];"
        :: "r"(dst), "l"(__cvta_generic_to_global(src)), "r"(bytes), "r"(mbar)
        : "memory");
}

#define LDSM4(r0, r1, r2, r3, a)                                            \
    asm volatile("ldmatrix.sync.aligned.m8n8.x4.shared.b16 "                \
                 "{%0,%1,%2,%3}, [%4];"                                     \
                 : "=r"(r0), "=r"(r1), "=r"(r2), "=r"(r3) : "r"(a))

#define MMA16816(d, a, b0v, b1v)                                            \
    asm volatile("mma.sync.aligned.m16n8k16.row.col.f32.f16.f16.f32 "       \
                 "{%0,%1,%2,%3}, {%4,%5,%6,%7}, {%8,%9}, {%0,%1,%2,%3};"    \
                 : "+f"((d)[0]), "+f"((d)[1]), "+f"((d)[2]), "+f"((d)[3])   \
                 : "r"((a)[0]), "r"((a)[1]), "r"((a)[2]), "r"((a)[3]),      \
                   "r"(b0v), "r"(b1v))

static __device__ __forceinline__ uint32_t pkf(float a, float b) {
    __half2 h = __floats2half2_rn(a, b);
    return *(uint32_t*)&h;
}
// packed half2 exp2
static __device__ __forceinline__ uint32_t h2ex2(uint32_t x) {
    uint32_t r;
    asm("ex2.approx.f16x2 %0, %1;" : "=r"(r) : "r"(x));
    return r;
}

#define ONESH2 0x3C003C00u   // half2(1.0, 1.0)

// ---------------------------------------------------------------------------
// Preprocessing: round X to fp16, write A tile image (hi only).
// ---------------------------------------------------------------------------
__global__ void xsplit(const float* __restrict__ x)
{
    int i = blockIdx.x * 256 + threadIdx.x;      // 8-float chunk index
    int l = i * 8;
    int m = l >> 10, k = l & (D_ - 1);
    float4 v0 = ((const float4*)x)[2 * i];
    float4 v1 = ((const float4*)x)[2 * i + 1];
    uint4 h4 = make_uint4(pkf(v0.x, v0.y), pkf(v0.z, v0.w),
                          pkf(v1.x, v1.y), pkf(v1.z, v1.w));
    size_t base = ((size_t)(m >> 7) * 16 + (k >> 6)) * 16384;
    int r = m & 127, c = (k >> 3) & 7;
    *(uint4*)&g_aimg[base + r * 128 + SWZ(c, r)] = h4;
}

// ---------------------------------------------------------------------------
// Preprocessing: transpose W, fp16 round, write B tile image.
// ---------------------------------------------------------------------------
__global__ void wsplit(const float* __restrict__ Wq,
                       const float* __restrict__ Wk,
                       const float* __restrict__ Wv)
{
    __shared__ float t[32][33];
    const int z = blockIdx.z;
    const float* W = (z == 0) ? Wq : (z == 1) ? Wk : Wv;
    const int n  = blockIdx.x * 32 + threadIdx.x;
    const int k0 = blockIdx.y * 32;
    #pragma unroll
    for (int dy = 0; dy < 32; dy += 8) {
        int k = k0 + threadIdx.y + dy;
        t[threadIdx.y + dy][threadIdx.x] = W[(size_t)k * D_ + n];
    }
    __syncthreads();
    const int kk = k0 + threadIdx.x;
    #pragma unroll
    for (int dy = 0; dy < 32; dy += 8) {
        int nn = blockIdx.x * 32 + threadIdx.y + dy;
        float v = t[threadIdx.x][threadIdx.y + dy];
        size_t base = ((size_t)(z * 8 + (nn >> 7)) * 16 + (kk >> 6)) * 16384;
        int r = nn & 127, c = (kk >> 3) & 7, byb = (kk & 7) * 2;
        *(unsigned short*)&g_bimg[base + r * 128 + SWZ(c, r) + byb] =
            __half_as_ushort(__float2half_rn(v));
    }
}

// ---------------------------------------------------------------------------
// QKV GEMM: 1-term fp16 (Ah*Bh).  BK=64 chunks, 16 iters, 3x32KB stages.
// z=2 epilogue writes V^T fp16 directly into the KV image.  (round-10 verified)
// ---------------------------------------------------------------------------
#define NK     16
#define SMEM_G (1024 + 3 * 32768)

__global__ __launch_bounds__(256, 2) void qkv_gemm_mma()
{
    extern __shared__ char smem[];
    const uint32_t sb = s2u(smem);
    const int tid  = threadIdx.x;
    const int warp = tid >> 5;
    const int lane = tid & 31;
    const int wm   = warp & 1;
    const int wn   = warp >> 1;

    const int n0 = blockIdx.x * 128;
    const int m0 = blockIdx.y * 128;
    const int z  = blockIdx.z;

    if (tid == 0) {
        mbar_init(sb + 0, 1);
        mbar_init(sb + 8, 1);
        mbar_init(sb + 16, 1);
    }
    __syncthreads();

    const unsigned char* Asrc = g_aimg + (size_t)blockIdx.y * 16 * 16384;
    const unsigned char* Bsrc = g_bimg + (size_t)(z * 8 + blockIdx.x) * 16 * 16384;

    if (tid == 0) {
        #pragma unroll
        for (int s = 0; s < 3; s++) {
            mbar_expect_tx(sb + 8 * s, 32768);
            bulk_g2s(sb + 1024 + s * 32768,         Asrc + s * 16384, 16384, sb + 8 * s);
            bulk_g2s(sb + 1024 + s * 32768 + 16384, Bsrc + s * 16384, 16384, sb + 8 * s);
        }
    }

    float acc[4][4][4];
    #pragma unroll
    for (int mi = 0; mi < 4; mi++)
        #pragma unroll
        for (int ni = 0; ni < 4; ni++)
            #pragma unroll
            for (int r = 0; r < 4; r++) acc[mi][ni][r] = 0.f;

    int aRow[4];
    #pragma unroll
    for (int mi = 0; mi < 4; mi++) aRow[mi] = wm * 64 + mi * 16 + (lane & 15);
    const int aG = (lane >> 4);
    int bRow[2];
    #pragma unroll
    for (int p = 0; p < 2; p++) bRow[p] = wn * 32 + p * 16 + (lane & 7) + ((lane & 16) >> 1);
    const int bG = (lane >> 3) & 1;

    for (int i = 0; i < NK; i++) {
        const int s = i % 3;
        mbar_wait(sb + 8 * s, (uint32_t)((i / 3) & 1));

        const uint32_t aBase = sb + 1024 + s * 32768;
        const uint32_t bBase = aBase + 16384;

        #pragma unroll
        for (int kstep = 0; kstep < 4; kstep++) {
            const int g0 = kstep * 2;

            uint32_t ah[4][4], bh2[2][4];
            #pragma unroll
            for (int mi = 0; mi < 4; mi++) {
                int r = aRow[mi];
                uint32_t ad = aBase + r * 128 + (((g0 + aG) ^ (r & 7)) << 4);
                LDSM4(ah[mi][0], ah[mi][1], ah[mi][2], ah[mi][3], ad);
            }
            #pragma unroll
            for (int p = 0; p < 2; p++) {
                int r = bRow[p];
                uint32_t bd = bBase + r * 128 + (((g0 + bG) ^ (r & 7)) << 4);
                LDSM4(bh2[p][0], bh2[p][1], bh2[p][2], bh2[p][3], bd);
            }
            #pragma unroll
            for (int mi = 0; mi < 4; mi++)
                #pragma unroll
                for (int ni = 0; ni < 4; ni++)
                    MMA16816(acc[mi][ni], ah[mi], bh2[ni >> 1][(ni & 1) * 2], bh2[ni >> 1][(ni & 1) * 2 + 1]);
        }

        __syncthreads();
        const int nx = i + 3;
        if (nx < NK && tid == 0) {
            mbar_expect_tx(sb + 8 * s, 32768);
            bulk_g2s(aBase, Asrc + nx * 16384, 16384, sb + 8 * s);
            bulk_g2s(bBase, Bsrc + nx * 16384, 16384, sb + 8 * s);
        }
    }

    // epilogue: z=0 -> Q image; z=1 -> Kh in KV image; z=2 -> V^T in KV image
    #pragma unroll
    for (int mi = 0; mi < 4; mi++) {
        #pragma unroll
        for (int ni = 0; ni < 4; ni++) {
            int m = m0 + wm * 64 + mi * 16 + (lane >> 2);
            int n = n0 + wn * 32 + ni * 8 + ((lane & 3) << 1);
            int h  = n >> 6;
            int dh = n & (DH_ - 1);
            #pragma unroll
            for (int half = 0; half < 2; half++) {
                int mm = m + half * 8;
                int b  = mm >> 11;
                int sq = mm & (S_ - 1);
                float v0 = acc[mi][ni][half * 2];
                float v1 = acc[mi][ni][half * 2 + 1];
                size_t bh = (size_t)b * H_ + h;
                if (z == 0) {
                    size_t ob = (bh * 16 + (sq >> 7)) * 16384
                              + (size_t)(sq & 127) * 128
                              + SWZ(dh >> 3, sq & 127) + (dh & 7) * 2;
                    *(uint32_t*)&g_qimg[ob] = pkf(v0, v1);
                } else if (z == 1) {
                    size_t ob = (bh * 32 + (sq >> 6)) * (size_t)KVSTRIDE
                              + (size_t)(sq & 63) * 128
                              + SWZ(dh >> 3, sq & 63) + (dh & 7) * 2;
                    *(uint32_t*)&g_kvimg[ob] = pkf(v0, v1);
                } else {
                    int sl = sq & 63;
                    size_t vb = (bh * 32 + (sq >> 6)) * (size_t)KVSTRIDE + 8192;
                    uint32_t o0 = (uint32_t)(dh * 128 + SWZ((sl >> 3) & 7, dh) + (sl & 7) * 2);
                    uint32_t o1 = (uint32_t)((dh + 1) * 128 + SWZ((sl >> 3) & 7, dh + 1) + (sl & 7) * 2);
                    *(unsigned short*)&g_kvimg[vb + o0] = __half_as_ushort(__float2half_rn(v0));
                    *(unsigned short*)&g_kvimg[vb + o1] = __half_as_ushort(__float2half_rn(v1));
                }
            }
        }
    }
}

// ---------------------------------------------------------------------------
// Tensor-core flash attention: 256 threads, 8 warps x 16 q-rows.
// 6 KV stages; block barrier every FOURTH tile, prefetching 4 tiles.
// (Sync at t multiple of 4 => all warps finished tiles <= t-1; stages
//  (t+2..t+5)%6 were last read at t-4..t-1 -> recyclable.)
// f16x2 exp; l via ones-MMA (round-16 verified).
// smem: mbars @ [0,1024); KV stages @1024+st*16K (6); Q @1024+96K.  113KB.
// ---------------------------------------------------------------------------
#define NKT    32
#define NSTA   6
#define OFF_Q  (1024 + NSTA * KVSTRIDE)
#define SMEM_A (OFF_Q + 16384)
#define L2E    1.4426950408889634f
#define CSC    (0.0625f * L2E)

__global__ __launch_bounds__(256, 2) void attn_mma(float* __restrict__ out)
{
    extern __shared__ char sm[];
    const uint32_t sb = s2u(sm);
    const int tid = threadIdx.x, warp = tid >> 5, lane = tid & 31;
    const int b = blockIdx.z, h = blockIdx.y, q0 = blockIdx.x * 128;
    const size_t bh = (size_t)(b * H_ + h);

    const unsigned char* Qsrc  = g_qimg + (bh * 16 + blockIdx.x) * 16384;
    const unsigned char* KVsrc = g_kvimg + bh * 32 * (size_t)KVSTRIDE;

    if (tid == 0) {
        mbar_init(sb + 0, 1);      // Q
        #pragma unroll
        for (int s = 0; s < NSTA; s++)
            mbar_init(sb + 8 + 8 * s, 1);   // KV stage s
    }
    __syncthreads();

    if (tid == 0) {
        mbar_expect_tx(sb, 16384);
        bulk_g2s(sb + OFF_Q, Qsrc, 16384, sb);
        #pragma unroll
        for (int s = 0; s < 2; s++) {
            mbar_expect_tx(sb + 8 + 8 * s, KVSTRIDE);
            bulk_g2s(sb + 1024 + s * KVSTRIDE, KVsrc + (size_t)s * KVSTRIDE,
                     KVSTRIDE, sb + 8 + 8 * s);
        }
    }

    mbar_wait(sb, 0);

    uint32_t Qh[4][4];
    {
        const int ar = warp * 16 + (lane & 15);
        const int ag = lane >> 4;
        #pragma unroll
        for (int kc = 0; kc < 4; kc++) {
            uint32_t ad = sb + OFF_Q + ar * 128 + (((kc * 2 + ag) ^ (ar & 7)) << 4);
            LDSM4(Qh[kc][0], Qh[kc][1], Qh[kc][2], Qh[kc][3], ad);
        }
    }

    float o[8][4];
    #pragma unroll
    for (int j = 0; j < 8; j++)
        #pragma unroll
        for (int r = 0; r < 4; r++) o[j][r] = 0.f;
    float lacc[4] = {0.f, 0.f, 0.f, 0.f};   // row-sum accumulator (via ones-MMA)
    float mm0 = 0.f, mm1 = 0.f;              // -max * log2(e), frozen after tile 0

    const int brb = (lane & 7) + ((lane & 16) >> 1);
    const int bg  = (lane >> 3) & 1;

    for (int t = 0; t < NKT; t++) {
        // Block barrier + quad-prefetch every fourth tile.
        if ((t & 3) == 0) {
            __syncthreads();
            if (tid == 0) {
                #pragma unroll
                for (int d = 2; d <= 5; d++) {
                    const int u = t + d;
                    if (u < NKT) {
                        const int st = u % NSTA;
                        mbar_expect_tx(sb + 8 + 8 * st, KVSTRIDE);
                        bulk_g2s(sb + 1024 + st * KVSTRIDE,
                                 KVsrc + (size_t)u * KVSTRIDE,
                                 KVSTRIDE, sb + 8 + 8 * st);
                    }
                }
            }
        }
        mbar_wait(sb + 8 + 8 * (t % NSTA), (uint32_t)((t / NSTA) & 1));

        const uint32_t kvb = sb + 1024 + (t % NSTA) * KVSTRIDE;

        // ---- S = Qh Kh^T (1 term) ----
        float s[8][4];
        #pragma unroll
        for (int j = 0; j < 8; j++)
            #pragma unroll
            for (int r = 0; r < 4; r++) s[j][r] = 0.f;

        #pragma unroll
        for (int kc = 0; kc < 4; kc++) {
            const int g = kc * 2 + bg;
            uint32_t kf[4][4];
            #pragma unroll
            for (int nt = 0; nt < 4; nt++) {
                int r = nt * 16 + brb;
                uint32_t off = r * 128 + ((g ^ (r & 7)) << 4);
                LDSM4(kf[nt][0], kf[nt][1], kf[nt][2], kf[nt][3], kvb + off);
            }
            #pragma unroll
            for (int nt = 0; nt < 4; nt++)
                #pragma unroll
                for (int h2 = 0; h2 < 2; h2++) {
                    int ni = nt * 2 + h2;
                    MMA16816(s[ni], Qh[kc], kf[nt][h2 * 2], kf[nt][h2 * 2 + 1]);
                }
        }

        // ---- frozen max (tile 0 only); store as -m*log2e ----
        if (t == 0) {
            float mt0 = -1e30f, mt1 = -1e30f;
            #pragma unroll
            for (int j = 0; j < 8; j++) {
                mt0 = fmaxf(mt0, fmaxf(s[j][0], s[j][1]));
                mt1 = fmaxf(mt1, fmaxf(s[j][2], s[j][3]));
            }
            mt0 *= 0.0625f; mt1 *= 0.0625f;
            mt0 = fmaxf(mt0, __shfl_xor_sync(0xFFFFFFFFu, mt0, 1));
            mt0 = fmaxf(mt0, __shfl_xor_sync(0xFFFFFFFFu, mt0, 2));
            mt1 = fmaxf(mt1, __shfl_xor_sync(0xFFFFFFFFu, mt1, 1));
            mt1 = fmaxf(mt1, __shfl_xor_sync(0xFFFFFFFFu, mt1, 2));
            mm0 = -mt0 * L2E;
            mm1 = -mt1 * L2E;
        }

        // ---- fused: per key-group f16x2 exp + PV MMAs + ones-MMA for l ----
        #pragma unroll
        for (int kc = 0; kc < 4; kc++) {
            const int g = kc * 2 + bg;
            uint32_t vh4[4][4];
            #pragma unroll
            for (int nt = 0; nt < 4; nt++) {
                int r = nt * 16 + brb;
                uint32_t off = r * 128 + ((g ^ (r & 7)) << 4);
                LDSM4(vh4[nt][0], vh4[nt][1], vh4[nt][2], vh4[nt][3], kvb + 8192 + off);
            }

            uint32_t Ahf[4];
            Ahf[0] = h2ex2(pkf(fmaf(s[2 * kc][0],     CSC, mm0),
                               fmaf(s[2 * kc][1],     CSC, mm0)));
            Ahf[1] = h2ex2(pkf(fmaf(s[2 * kc][2],     CSC, mm1),
                               fmaf(s[2 * kc][3],     CSC, mm1)));
            Ahf[2] = h2ex2(pkf(fmaf(s[2 * kc + 1][0], CSC, mm0),
                               fmaf(s[2 * kc + 1][1], CSC, mm0)));
            Ahf[3] = h2ex2(pkf(fmaf(s[2 * kc + 1][2], CSC, mm1),
                               fmaf(s[2 * kc + 1][3], CSC, mm1)));

            MMA16816(lacc, Ahf, ONESH2, ONESH2);

            #pragma unroll
            for (int nt = 0; nt < 4; nt++)
                #pragma unroll
                for (int h2 = 0; h2 < 2; h2++) {
                    int ni = nt * 2 + h2;
                    MMA16816(o[ni], Ahf, vh4[nt][h2 * 2], vh4[nt][h2 * 2 + 1]);
                }
        }
    }

    // ---- epilogue (lacc[0] = row sum, lacc[2] = row+8) ----
    const float i0 = 1.0f / lacc[0], i1 = 1.0f / lacc[2];

    const int q = q0 + warp * 16 + (lane >> 2);
    float* op = out + ((size_t)b * S_ + q) * D_ + h * DH_;
    #pragma unroll
    for (int j = 0; j < 8; j++) {
        int dh = j * 8 + ((lane & 3) << 1);
        *(float2*)(op + dh)          = make_float2(o[j][0] * i0, o[j][1] * i0);
        *(float2*)(op + 8 * D_ + dh) = make_float2(o[j][2] * i1, o[j][3] * i1);
    }
}

// ---------------------------------------------------------------------------
// Launch
// ---------------------------------------------------------------------------
extern "C" void kernel_launch(void* const* d_in, const int* in_sizes, int n_in,
                              void* d_out, int out_size)
{
    const float* x  = (const float*)d_in[0];
    const float* wq = (const float*)d_in[1];
    const float* wk = (const float*)d_in[2];
    const float* wv = (const float*)d_in[3];
    float* out = (float*)d_out;

    static bool attr_set = false;
    if (!attr_set) {
        cudaFuncSetAttribute(qkv_gemm_mma,
                             cudaFuncAttributeMaxDynamicSharedMemorySize, SMEM_G);
        cudaFuncSetAttribute(attn_mma,
                             cudaFuncAttributeMaxDynamicSharedMemorySize, SMEM_A);
        attr_set = true;
    }

    xsplit<<<(M_ * D_ / 8) / 256, 256>>>(x);
    wsplit<<<dim3(32, 32, 3), dim3(32, 8)>>>(wq, wk, wv);
    qkv_gemm_mma<<<dim3(D_ / 128, M_ / 128, 3), 256, SMEM_G>>>();
    attn_mma<<<dim3(S_ / 128, H_, B_), 256, SMEM_A>>>(out);
}